// round 5
// baseline (speedup 1.0000x reference)
#include <cuda_runtime.h>

// TreeNLLLoss, chain-split into two kernels per replay:
//   A) pre_kernel:  idx streams -> label gathers -> write per-edge packed
//      pidx16[e] = 16*tc+tp (ushort) and uoff[e] = 16*child+tc (int), coalesced.
//   B) fused_kernel: coalesced loads of pidx/uoff -> 8 independent random
//      gathers per thread (no dependent-load prelude) -> reduce -> finalize.
//
//   loss = sum_e edge_pot[e, 16*tc+tp] + sum_e unary[child_e, tc] + unary[root, l_root]
//   out  = -(loss - partition)
// E = 1,000,000 edges, N = 1,000,001 nodes, C = 16.

#define C 16
#define EPT 4
#define THREADS 256
#define MAX_BLOCKS 4096
#define E_MAX 1000448   // >= 1,000,000, padded to multiple of 256*4

__device__ unsigned short g_pidx[E_MAX];   // 2 MB
__device__ int            g_uoff[E_MAX];   // 4 MB
__device__ float          g_partials[MAX_BLOCKS];
__device__ unsigned       g_count = 0;     // returns to 0 each replay

struct ushort4_t { unsigned short x, y, z, w; };

// ── Kernel A: resolve labels, write packed offsets (coalesced) ──
__global__ void __launch_bounds__(THREADS)
pre_kernel(const int* __restrict__ labels,
           const int* __restrict__ child_idx,
           const int* __restrict__ parent_idx,
           int E)
{
    const int tid  = blockIdx.x * THREADS + threadIdx.x;
    const int base = tid * EPT;

    if (base + EPT <= E) {
        int4 c4 = __ldg((const int4*)child_idx  + tid);
        int4 p4 = __ldg((const int4*)parent_idx + tid);
        int c[EPT] = {c4.x, c4.y, c4.z, c4.w};
        int p[EPT] = {p4.x, p4.y, p4.z, p4.w};

        int tc[EPT], tp[EPT];
        #pragma unroll
        for (int j = 0; j < EPT; j++) {
            tc[j] = __ldg(&labels[c[j]]);
            tp[j] = __ldg(&labels[p[j]]);
        }

        ushort4_t pk;
        pk.x = (unsigned short)(tc[0] * C + tp[0]);
        pk.y = (unsigned short)(tc[1] * C + tp[1]);
        pk.z = (unsigned short)(tc[2] * C + tp[2]);
        pk.w = (unsigned short)(tc[3] * C + tp[3]);
        ((ushort4_t*)g_pidx)[tid] = pk;

        int4 uo;
        uo.x = c[0] * C + tc[0];
        uo.y = c[1] * C + tc[1];
        uo.z = c[2] * C + tc[2];
        uo.w = c[3] * C + tc[3];
        ((int4*)g_uoff)[tid] = uo;
    } else {
        for (int j = 0; j < EPT; j++) {
            int e = base + j;
            if (e < E) {
                int ci = __ldg(&child_idx[e]);
                int pi = __ldg(&parent_idx[e]);
                int tc = __ldg(&labels[ci]);
                int tp = __ldg(&labels[pi]);
                g_pidx[e] = (unsigned short)(tc * C + tp);
                g_uoff[e] = ci * C + tc;
            }
        }
    }
}

// ── Kernel B: independent gathers + reduce + finalize ──
__global__ void __launch_bounds__(THREADS)
fused_kernel(const float* __restrict__ edge_pot,
             const float* __restrict__ unary,
             const int*   __restrict__ labels,
             const int*   __restrict__ root_idx,
             const float* __restrict__ partition,
             float* __restrict__ out,
             int E)
{
    const int tid  = blockIdx.x * THREADS + threadIdx.x;
    const int base = tid * EPT;

    float s = 0.0f;

    if (base + EPT <= E) {
        ushort4_t pk = ((const ushort4_t*)g_pidx)[tid];
        int4      uo = ((const int4*)g_uoff)[tid];
        int pki[EPT] = {pk.x, pk.y, pk.z, pk.w};
        int uoi[EPT] = {uo.x, uo.y, uo.z, uo.w};

        // 8 fully independent random gathers, issued back-to-back
        float ep[EPT], cu[EPT];
        #pragma unroll
        for (int j = 0; j < EPT; j++)
            ep[j] = __ldcs(&edge_pot[(size_t)(base + j) * (C * C) + pki[j]]);
        #pragma unroll
        for (int j = 0; j < EPT; j++)
            cu[j] = __ldg(&unary[uoi[j]]);

        #pragma unroll
        for (int j = 0; j < EPT; j++) s += ep[j] + cu[j];
    } else {
        for (int j = 0; j < EPT; j++) {
            int e = base + j;
            if (e < E) {
                s += __ldcs(&edge_pot[(size_t)e * (C * C) + g_pidx[e]]);
                s += __ldg(&unary[g_uoff[e]]);
            }
        }
    }

    // ── block reduce ──
    #pragma unroll
    for (int off = 16; off > 0; off >>= 1)
        s += __shfl_down_sync(0xffffffffu, s, off);

    __shared__ float warp_sums[THREADS / 32];
    const int lane = threadIdx.x & 31;
    const int wid  = threadIdx.x >> 5;
    if (lane == 0) warp_sums[wid] = s;
    __syncthreads();

    if (wid == 0) {
        float t = (lane < THREADS / 32) ? warp_sums[lane] : 0.0f;
        #pragma unroll
        for (int off = 4; off > 0; off >>= 1)
            t += __shfl_down_sync(0xffffffffu, t, off);
        if (lane == 0) g_partials[blockIdx.x] = t;
    }

    // ── last-block-done finalize ──
    __shared__ bool is_last;
    __threadfence();
    if (threadIdx.x == 0) {
        unsigned ticket = atomicAdd(&g_count, 1u);
        is_last = (ticket == gridDim.x - 1);
    }
    __syncthreads();

    if (is_last) {
        double acc = 0.0;
        for (int i = threadIdx.x; i < (int)gridDim.x; i += THREADS)
            acc += (double)__ldcg(&g_partials[i]);

        #pragma unroll
        for (int off = 16; off > 0; off >>= 1)
            acc += __shfl_down_sync(0xffffffffu, acc, off);

        __shared__ double dwarp[THREADS / 32];
        if (lane == 0) dwarp[wid] = acc;
        __syncthreads();

        if (wid == 0) {
            double t = (lane < THREADS / 32) ? dwarp[lane] : 0.0;
            #pragma unroll
            for (int off = 4; off > 0; off >>= 1)
                t += __shfl_down_sync(0xffffffffu, t, off);
            if (lane == 0) {
                int r = __ldg(root_idx);
                float root_unary = __ldg(&unary[(size_t)r * C + __ldg(&labels[r])]);
                double loss = t + (double)root_unary;
                out[0] = -(float)(loss - (double)__ldg(partition));
                g_count = 0;   // reset for next replay
            }
        }
    }
}

extern "C" void kernel_launch(void* const* d_in, const int* in_sizes, int n_in,
                              void* d_out, int out_size)
{
    const float* edge_pot   = (const float*)d_in[0];
    const float* unary      = (const float*)d_in[1];
    const int*   labels     = (const int*)d_in[2];
    const int*   child_idx  = (const int*)d_in[3];
    const int*   parent_idx = (const int*)d_in[4];
    const int*   root_idx   = (const int*)d_in[5];
    const float* partition  = (const float*)d_in[6];
    float* out = (float*)d_out;

    int E = in_sizes[3];

    int per_block = THREADS * EPT;
    int blocks = (E + per_block - 1) / per_block;
    if (blocks > MAX_BLOCKS) blocks = MAX_BLOCKS;  // E=1e6 -> 977

    pre_kernel<<<blocks, THREADS>>>(labels, child_idx, parent_idx, E);
    fused_kernel<<<blocks, THREADS>>>(edge_pot, unary, labels,
                                      root_idx, partition, out, E);
}

// round 6
// speedup vs baseline: 1.0486x; 1.0486x over previous
#include <cuda_runtime.h>

// TreeNLLLoss, two kernels per replay:
//   A) node_sweep: sequential sweep over nodes:
//        node_val[v] = unary[16v + labels[v]]  (4 MB, L2-resident)
//        labels8[v]  = (u8)labels[v]           (1 MB, L2-resident)
//      Converts the 64 MB random unary gather into a streamed sweep + tiny gather.
//   B) edge_kernel: per edge: gather tc,tp from labels8, edge_pot[e,16tc+tp]
//      via __ldcs (compulsory 128 MB line stream, evict-first), node_val[child]
//      from L2. Block reduce -> last-block finalize.
//
//   loss = sum_e edge_pot[e,16tc+tp] + sum_e node_val[child_e] + node_val[root]
//   out  = -(loss - partition)
// E = 1,000,000 edges, N = 1,000,001 nodes, C = 16.

#define C 16
#define EPT 8
#define THREADS 256
#define MAX_BLOCKS 4096
#define N_MAX 1000960   // >= 1,000,001, multiple of 1024

__device__ float         g_node_val[N_MAX];   // 4 MB
__device__ unsigned char g_labels8[N_MAX];    // 1 MB
__device__ float         g_partials[MAX_BLOCKS];
__device__ unsigned      g_count = 0;         // returns to 0 each replay

// ── Kernel A: sequential node sweep ──
__global__ void __launch_bounds__(THREADS)
node_sweep(const float* __restrict__ unary,
           const int*   __restrict__ labels,
           int N)
{
    int t = blockIdx.x * THREADS + threadIdx.x;   // 4 nodes per thread
    int base = t * 4;
    if (base + 4 <= N) {
        int4 l = __ldg((const int4*)labels + t);
        float4 nv;
        nv.x = __ldg(&unary[(size_t)(base + 0) * C + l.x]);
        nv.y = __ldg(&unary[(size_t)(base + 1) * C + l.y]);
        nv.z = __ldg(&unary[(size_t)(base + 2) * C + l.z]);
        nv.w = __ldg(&unary[(size_t)(base + 3) * C + l.w]);
        *((float4*)(g_node_val + base)) = nv;
        *((uchar4*)(g_labels8 + base)) =
            make_uchar4((unsigned char)l.x, (unsigned char)l.y,
                        (unsigned char)l.z, (unsigned char)l.w);
    } else {
        for (int v = base; v < N; v++) {
            int lab = __ldg(&labels[v]);
            g_node_val[v] = __ldg(&unary[(size_t)v * C + lab]);
            g_labels8[v]  = (unsigned char)lab;
        }
    }
}

// ── Kernel B: edge gathers + reduce + finalize ──
__global__ void __launch_bounds__(THREADS)
edge_kernel(const float* __restrict__ edge_pot,
            const int*   __restrict__ child_idx,
            const int*   __restrict__ parent_idx,
            const int*   __restrict__ root_idx,
            const float* __restrict__ partition,
            float* __restrict__ out,
            int E)
{
    const int tid  = blockIdx.x * THREADS + threadIdx.x;
    const int base = tid * EPT;

    float s = 0.0f;

    if (base + EPT <= E) {
        // coalesced index streams
        int4 c4a = __ldg((const int4*)child_idx  + 2 * tid);
        int4 c4b = __ldg((const int4*)child_idx  + 2 * tid + 1);
        int4 p4a = __ldg((const int4*)parent_idx + 2 * tid);
        int4 p4b = __ldg((const int4*)parent_idx + 2 * tid + 1);
        int c[EPT] = {c4a.x, c4a.y, c4a.z, c4a.w, c4b.x, c4b.y, c4b.z, c4b.w};
        int p[EPT] = {p4a.x, p4a.y, p4a.z, p4a.w, p4b.x, p4b.y, p4b.z, p4b.w};

        // label gathers from packed 1 MB array (L2-resident)
        int tc[EPT], tp[EPT];
        #pragma unroll
        for (int j = 0; j < EPT; j++) {
            tc[j] = (int)__ldg(&g_labels8[c[j]]);
            tp[j] = (int)__ldg(&g_labels8[p[j]]);
        }

        // edge_pot: compulsory DRAM line stream, evict-first
        float ep[EPT];
        #pragma unroll
        for (int j = 0; j < EPT; j++)
            ep[j] = __ldcs(&edge_pot[(size_t)(base + j) * (C * C) + tc[j] * C + tp[j]]);

        // unary term: gather from 4 MB L2-resident node_val
        float cu[EPT];
        #pragma unroll
        for (int j = 0; j < EPT; j++)
            cu[j] = __ldg(&g_node_val[c[j]]);

        #pragma unroll
        for (int j = 0; j < EPT; j++) s += ep[j] + cu[j];
    } else {
        for (int j = 0; j < EPT; j++) {
            int e = base + j;
            if (e < E) {
                int ci = __ldg(&child_idx[e]);
                int pi = __ldg(&parent_idx[e]);
                int tc = (int)__ldg(&g_labels8[ci]);
                int tp = (int)__ldg(&g_labels8[pi]);
                s += __ldcs(&edge_pot[(size_t)e * (C * C) + tc * C + tp]);
                s += __ldg(&g_node_val[ci]);
            }
        }
    }

    // ── block reduce ──
    #pragma unroll
    for (int off = 16; off > 0; off >>= 1)
        s += __shfl_down_sync(0xffffffffu, s, off);

    __shared__ float warp_sums[THREADS / 32];
    const int lane = threadIdx.x & 31;
    const int wid  = threadIdx.x >> 5;
    if (lane == 0) warp_sums[wid] = s;
    __syncthreads();

    if (wid == 0) {
        float t = (lane < THREADS / 32) ? warp_sums[lane] : 0.0f;
        #pragma unroll
        for (int off = 4; off > 0; off >>= 1)
            t += __shfl_down_sync(0xffffffffu, t, off);
        if (lane == 0) g_partials[blockIdx.x] = t;
    }

    // ── last-block-done finalize ──
    __shared__ bool is_last;
    __threadfence();
    if (threadIdx.x == 0) {
        unsigned ticket = atomicAdd(&g_count, 1u);
        is_last = (ticket == gridDim.x - 1);
    }
    __syncthreads();

    if (is_last) {
        double acc = 0.0;
        for (int i = threadIdx.x; i < (int)gridDim.x; i += THREADS)
            acc += (double)__ldcg(&g_partials[i]);

        #pragma unroll
        for (int off = 16; off > 0; off >>= 1)
            acc += __shfl_down_sync(0xffffffffu, acc, off);

        __shared__ double dwarp[THREADS / 32];
        if (lane == 0) dwarp[wid] = acc;
        __syncthreads();

        if (wid == 0) {
            double t = (lane < THREADS / 32) ? dwarp[lane] : 0.0;
            #pragma unroll
            for (int off = 4; off > 0; off >>= 1)
                t += __shfl_down_sync(0xffffffffu, t, off);
            if (lane == 0) {
                int r = __ldg(root_idx);
                double loss = t + (double)g_node_val[r];
                out[0] = -(float)(loss - (double)__ldg(partition));
                g_count = 0;   // reset for next replay
            }
        }
    }
}

extern "C" void kernel_launch(void* const* d_in, const int* in_sizes, int n_in,
                              void* d_out, int out_size)
{
    const float* edge_pot   = (const float*)d_in[0];
    const float* unary      = (const float*)d_in[1];
    const int*   labels     = (const int*)d_in[2];
    const int*   child_idx  = (const int*)d_in[3];
    const int*   parent_idx = (const int*)d_in[4];
    const int*   root_idx   = (const int*)d_in[5];
    const float* partition  = (const float*)d_in[6];
    float* out = (float*)d_out;

    int N = in_sizes[2];
    int E = in_sizes[3];

    int sweep_blocks = (N + THREADS * 4 - 1) / (THREADS * 4);
    node_sweep<<<sweep_blocks, THREADS>>>(unary, labels, N);

    int per_block = THREADS * EPT;
    int blocks = (E + per_block - 1) / per_block;
    if (blocks > MAX_BLOCKS) blocks = MAX_BLOCKS;  // E=1e6 -> 489

    edge_kernel<<<blocks, THREADS>>>(edge_pot, child_idx, parent_idx,
                                     root_idx, partition, out, E);
}